// round 15
// baseline (speedup 1.0000x reference)
#include <cuda_runtime.h>
#include <cuda_fp16.h>
#include <float.h>
#include <cstdint>

#define B_   8
#define C_   64
#define N_   4096
#define K_   20
#define M_   8
#define OUTC 64
#define CM   512          // C_*M_
#define PTS  (B_*N_)      // 32768

// Scratch (allocation-free rule: __device__ globals)
__device__ __align__(16) __half g_ftH[B_*N_*C_];           // feature fp16 [b][n][c] (4 MB)
__device__ __align__(16) __half g_aggH[(size_t)PTS*CM];    // agg fp16 [pt][pos]    (32 MB)
__device__ __align__(16) __half g_wh[CM*OUTC];             // conv_w fp16 [oc][pos] (64 KB)
__device__ __align__(16) float4 g_x4[PTS];                 // packed coords (512 KB)

__device__ __forceinline__ uint32_t smem_u32(const void* p) {
    uint32_t a;
    asm("{ .reg .u64 t; cvta.to.shared.u64 t, %1; cvt.u32.u64 %0, t; }" : "=r"(a) : "l"(p));
    return a;
}

// ===========================================================================
// K1: feature (B,C,N) fp32 -> g_ftH (B,N,C) fp16
// ===========================================================================
__global__ void __launch_bounds__(256) k_transpose_feat(const float* __restrict__ feat) {
    __shared__ float tile[128][65];
    const int b   = blockIdx.y;
    const int n0  = blockIdx.x * 128;
    const int tid = threadIdx.x;
    const float* fb = feat + (size_t)b * C_ * N_;
    #pragma unroll
    for (int i = 0; i < 8; i++) {
        const int idx = tid + i * 256;
        const int c   = idx >> 5;
        const int n4  = idx & 31;
        const float4 v = *(const float4*)(fb + (size_t)c * N_ + n0 + n4 * 4);
        tile[n4*4+0][c] = v.x;
        tile[n4*4+1][c] = v.y;
        tile[n4*4+2][c] = v.z;
        tile[n4*4+3][c] = v.w;
    }
    __syncthreads();
    __half* ob = g_ftH + (size_t)b * N_ * C_;
    #pragma unroll
    for (int i = 0; i < 4; i++) {
        const int idx = tid + i * 256;
        const int n   = idx >> 3;
        const int q   = idx & 7;
        const float* src = &tile[n][q * 8];
        __half2 h[4];
        #pragma unroll
        for (int j = 0; j < 4; j++) h[j] = __floats2half2_rn(src[2*j], src[2*j+1]);
        *(uint4*)(ob + (size_t)(n0 + n) * C_ + q * 8) = *(uint4*)h;
    }
}

// ===========================================================================
// Prep: conv_w -> fp16 with the pos-permutation matching K3's fragment store
//   pos: l = pos>>4, q = pos&15, ct = q>>2, e = q&3
//   c = 16*ct + (l>>2) + 8*(e>>1); m = 2*(l&3) + (e&1); j = c*8 + m
// Also x -> packed float4 per point.
// ===========================================================================
__global__ void k_prep(const float* __restrict__ w, const float* __restrict__ x) {
    const int i = blockIdx.x * blockDim.x + threadIdx.x;   // 0 .. 32767
    const int oc  = i >> 9;
    const int pos = i & 511;
    const int l   = pos >> 4;
    const int q   = pos & 15;
    const int ct  = q >> 2;
    const int e   = q & 3;
    const int c   = 16 * ct + (l >> 2) + ((e >> 1) << 3);
    const int m   = ((l & 3) << 1) + (e & 1);
    g_wh[i] = __float2half(w[(oc << 9) + c * 8 + m]);

    const int b = i >> 12;
    const int n = i & (N_ - 1);
    const float* xb = x + (size_t)b * 3 * N_;
    g_x4[i] = make_float4(xb[n], xb[N_ + n], xb[2*N_ + n], 0.f);
}

// ===========================================================================
// K3: warp-per-point, HMMA aggregation.
//   f_s[k 0..31][c 0..63] fp16 (stride 72 halves), filled by cp.async rows,
//   pad rows 20..31 zeroed. p fp16 [m][k] (stride 40). 8 mma per point.
// ===========================================================================
#define FS 72      // halves per f_s row (64 + 8; 144 B -> conflict-free ldmatrix)
#define PS 40      // halves per p row   (32 + 8;  80 B)

__global__ void __launch_bounds__(256) k_agg(
    const int*   __restrict__ nidx,          // int32 (JAX x64 disabled)
    const float* __restrict__ kern)
{
    __shared__ __half f_s[8][32 * FS];       // 8 x 4608 B
    __shared__ __half p_s[8][8 * PS];        // 8 x  640 B

    const int warp = threadIdx.x >> 5;
    const int lane = threadIdx.x & 31;
    const int pt   = blockIdx.x * 8 + warp;
    const int b    = pt >> 12;

    __half* fw = f_s[warp];
    __half* pw = p_s[warp];

    // ---- zero pad rows k=20..31 (108 x 16B starting at byte 20*144) ----
    {
        const uint4 z = make_uint4(0, 0, 0, 0);
        char* base = (char*)fw + 20 * 144;
        #pragma unroll
        for (int i = lane; i < 108; i += 32) *(uint4*)(base + i * 16) = z;
    }

    // ---- indices + x gather ----
    int ik = 0;
    float x0 = 0.f, x1 = 0.f, x2 = 0.f;
    if (lane < K_) {
        ik = nidx[pt * K_ + lane] & (N_ - 1);
        const float4 xv = g_x4[(b << 12) + ik];
        x0 = xv.x; x1 = xv.y; x2 = xv.z;
    }

    // ---- feature gathers: one coalesced 128B row per cp.async step ----
    const __half* ftb = g_ftH + ((size_t)b << 12) * C_;
    const uint32_t fw_u = smem_u32(fw);
    #pragma unroll
    for (int k = 0; k < K_; k++) {
        const int ii = __shfl_sync(0xFFFFFFFFu, ik, k);
        asm volatile("cp.async.ca.shared.global [%0], [%1], 4;" ::
            "r"(fw_u + k * 144 + lane * 4),
            "l"(ftb + (size_t)ii * C_ + lane * 2));
    }
    asm volatile("cp.async.commit_group;");

    // ---- softmax (overlaps the async copies) ----
    const float r0 = x0 - __shfl_sync(0xFFFFFFFFu, x0, 0);
    const float r1 = x1 - __shfl_sync(0xFFFFFFFFu, x1, 0);
    const float r2 = x2 - __shfl_sync(0xFFFFFFFFu, x2, 0);

    float px[8];
    #pragma unroll
    for (int m = 0; m < M_; m++) {
        float v = r0 * kern[m] + r1 * kern[M_ + m] + r2 * kern[2*M_ + m];
        if (lane == 0 && m == 0) v += 1.0f;       // one_pad
        px[m] = v;
    }
    #pragma unroll
    for (int m = 0; m < M_; m++) {
        const float e = (lane < K_) ? __expf(px[m]) : 0.f;
        float s = e;
        #pragma unroll
        for (int o = 16; o > 0; o >>= 1)
            s += __shfl_xor_sync(0xFFFFFFFFu, s, o);
        px[m] = e * (1.0f / s);                   // lanes >= 20 get exactly 0
    }
    // write p fp16: [m][k], all 32 lanes (k>=20 columns become zero)
    #pragma unroll
    for (int m = 0; m < M_; m++)
        pw[m * PS + lane] = __float2half(px[m]);

    asm volatile("cp.async.wait_group 0;");
    __syncwarp();

    // ---- B fragments (K4-proven pattern: [n=m][k] rows, ldmatrix.x2) ----
    uint32_t bfr[2][2];
    #pragma unroll
    for (int ks = 0; ks < 2; ks++) {
        const uint32_t addr = smem_u32(
            pw + (lane & 7) * PS + ks * 16 + ((lane >> 3) & 1) * 8);
        asm volatile("ldmatrix.sync.aligned.m8n8.x2.shared.b16 {%0,%1}, [%2];"
                     : "=r"(bfr[ks][0]), "=r"(bfr[ks][1]) : "r"(addr));
    }

    // ---- A fragments via ldmatrix.x4.trans + mma ----
    float acc[4][4];
    #pragma unroll
    for (int ct = 0; ct < 4; ct++)
        #pragma unroll
        for (int r = 0; r < 4; r++) acc[ct][r] = 0.f;

    #pragma unroll
    for (int ks = 0; ks < 2; ks++) {
        const int row_k  = ks * 16 + ((lane >> 4) & 1) * 8 + (lane & 7);
        const int c_base = ((lane >> 3) & 1) * 8;
        #pragma unroll
        for (int ct = 0; ct < 4; ct++) {
            uint32_t a[4];
            const uint32_t addr = smem_u32(fw + row_k * FS + ct * 16 + c_base);
            asm volatile("ldmatrix.sync.aligned.m8n8.x4.trans.shared.b16 "
                         "{%0,%1,%2,%3}, [%4];"
                         : "=r"(a[0]), "=r"(a[1]), "=r"(a[2]), "=r"(a[3])
                         : "r"(addr));
            asm volatile(
                "mma.sync.aligned.m16n8k16.row.col.f32.f16.f16.f32 "
                "{%0,%1,%2,%3}, {%4,%5,%6,%7}, {%8,%9}, {%0,%1,%2,%3};"
                : "+f"(acc[ct][0]), "+f"(acc[ct][1]),
                  "+f"(acc[ct][2]), "+f"(acc[ct][3])
                : "r"(a[0]), "r"(a[1]), "r"(a[2]), "r"(a[3]),
                  "r"(bfr[ks][0]), "r"(bfr[ks][1]));
        }
    }

    // ---- store: pos = lane*16 + ct*4 + e (perm matched by k_prep) ----
    __half2 h[8];
    #pragma unroll
    for (int ct = 0; ct < 4; ct++) {
        h[2*ct]     = __floats2half2_rn(acc[ct][0], acc[ct][1]);
        h[2*ct + 1] = __floats2half2_rn(acc[ct][2], acc[ct][3]);
    }
    __half* dst = g_aggH + (size_t)pt * CM + lane * 16;
    *(uint4*)(dst)     = *(uint4*)(h);
    *(uint4*)(dst + 8) = *(uint4*)(h + 4);
}

// ===========================================================================
// K4: HMMA fp16 GEMM, 64pt x 64oc tiles (grid 512), cp.async double buffer
// ===========================================================================
#define AS_STRIDE 72
#define BS_STRIDE 72
#define OS_STRIDE 68

struct Stage { __half a[64 * AS_STRIDE]; __half b[64 * BS_STRIDE]; };

__global__ void __launch_bounds__(256) k_gemm_hmma(
    const float* __restrict__ bias,
    const float* __restrict__ feat,
    float* __restrict__ out)
{
    __shared__ union {
        Stage st[2];
        float o[64 * OS_STRIDE];
    } sm;

    const int tid  = threadIdx.x;
    const int wid  = tid >> 5;
    const int lane = tid & 31;
    const int warp_m = (wid & 3) * 16;
    const int warp_n = (wid >> 2) * 32;
    const int ptBase = blockIdx.x * 64;

    float acc[4][4];
    #pragma unroll
    for (int ni = 0; ni < 4; ni++)
        #pragma unroll
        for (int r = 0; r < 4; r++) acc[ni][r] = 0.f;

    const __half* aSrc = g_aggH + (size_t)ptBase * CM;

    auto load_chunk = [&](int s, int kc) {
        #pragma unroll
        for (int i = 0; i < 2; i++) {
            const int c   = tid + i * 256;
            const int row = c >> 3;
            const int c8  = c & 7;
            asm volatile("cp.async.cg.shared.global [%0], [%1], 16;" ::
                "r"(smem_u32(sm.st[s].a + row * AS_STRIDE + c8 * 8)),
                "l"(aSrc + (size_t)row * CM + kc + c8 * 8));
        }
        #pragma unroll
        for (int i = 0; i < 2; i++) {
            const int c   = tid + i * 256;
            const int row = c >> 3;
            const int c8  = c & 7;
            asm volatile("cp.async.cg.shared.global [%0], [%1], 16;" ::
                "r"(smem_u32(sm.st[s].b + row * BS_STRIDE + c8 * 8)),
                "l"(g_wh + (size_t)row * CM + kc + c8 * 8));
        }
    };

    load_chunk(0, 0);
    asm volatile("cp.async.commit_group;");

    for (int kc8 = 0; kc8 < 8; kc8++) {
        if (kc8 < 7) {
            load_chunk((kc8 + 1) & 1, (kc8 + 1) * 64);
            asm volatile("cp.async.commit_group;");
            asm volatile("cp.async.wait_group 1;");
        } else {
            asm volatile("cp.async.wait_group 0;");
        }
        __syncthreads();

        const Stage& st = sm.st[kc8 & 1];
        #pragma unroll
        for (int ks = 0; ks < 4; ks++) {
            uint32_t a[4];
            {
                const uint32_t addr = smem_u32(
                    st.a + (warp_m + (lane & 15)) * AS_STRIDE
                         + ks * 16 + (lane >> 4) * 8);
                asm volatile("ldmatrix.sync.aligned.m8n8.x4.shared.b16 "
                             "{%0,%1,%2,%3}, [%4];"
                             : "=r"(a[0]), "=r"(a[1]), "=r"(a[2]), "=r"(a[3])
                             : "r"(addr));
            }
            uint32_t bfr[4][2];
            #pragma unroll
            for (int ni = 0; ni < 4; ni++) {
                const uint32_t addr = smem_u32(
                    st.b + (warp_n + ni * 8 + (lane & 7)) * BS_STRIDE
                         + ks * 16 + ((lane >> 3) & 1) * 8);
                asm volatile("ldmatrix.sync.aligned.m8n8.x2.shared.b16 "
                             "{%0,%1}, [%2];"
                             : "=r"(bfr[ni][0]), "=r"(bfr[ni][1])
                             : "r"(addr));
            }
            #pragma unroll
            for (int ni = 0; ni < 4; ni++) {
                asm volatile(
                    "mma.sync.aligned.m16n8k16.row.col.f32.f16.f16.f32 "
                    "{%0,%1,%2,%3}, {%4,%5,%6,%7}, {%8,%9}, {%0,%1,%2,%3};"
                    : "+f"(acc[ni][0]), "+f"(acc[ni][1]),
                      "+f"(acc[ni][2]), "+f"(acc[ni][3])
                    : "r"(a[0]), "r"(a[1]), "r"(a[2]), "r"(a[3]),
                      "r"(bfr[ni][0]), "r"(bfr[ni][1]));
            }
        }
        __syncthreads();
    }

    {
        const int r  = lane >> 2;
        const int cp = (lane & 3) * 2;
        #pragma unroll
        for (int ni = 0; ni < 4; ni++) {
            const int pt0 = warp_m + r;
            const int oc0 = warp_n + ni * 8 + cp;
            sm.o[oc0 * OS_STRIDE + pt0]           = acc[ni][0];
            sm.o[(oc0 + 1) * OS_STRIDE + pt0]     = acc[ni][1];
            sm.o[oc0 * OS_STRIDE + pt0 + 8]       = acc[ni][2];
            sm.o[(oc0 + 1) * OS_STRIDE + pt0 + 8] = acc[ni][3];
        }
    }
    __syncthreads();

    const int b  = ptBase >> 12;
    const int n0 = ptBase & (N_ - 1);
    #pragma unroll
    for (int i = 0; i < 4; i++) {
        const int c    = tid + i * 256;
        const int oc   = c >> 4;
        const int col4 = (c & 15) * 4;
        const float* src = sm.o + oc * OS_STRIDE + col4;
        const size_t o = ((size_t)(b * OUTC + oc)) * N_ + n0 + col4;
        const float4 f = *(const float4*)(feat + o);
        const float bb = bias[oc];
        float4 v;
        v.x = src[0] + bb; v.x = (v.x > 0.f ? v.x : 0.2f * v.x) + f.x;
        v.y = src[1] + bb; v.y = (v.y > 0.f ? v.y : 0.2f * v.y) + f.y;
        v.z = src[2] + bb; v.z = (v.z > 0.f ? v.z : 0.2f * v.z) + f.z;
        v.w = src[3] + bb; v.w = (v.w > 0.f ? v.w : 0.2f * v.w) + f.w;
        *(float4*)(out + o) = v;
    }
}

// ===========================================================================
extern "C" void kernel_launch(void* const* d_in, const int* in_sizes, int n_in,
                              void* d_out, int out_size) {
    const float* x    = (const float*)d_in[0];
    const float* feat = (const float*)d_in[1];
    const int*   nidx = (const int*)d_in[2];     // int32: JAX x64 is disabled
    const float* kern = (const float*)d_in[3];
    const float* w    = (const float*)d_in[4];
    const float* bias = (const float*)d_in[5];
    float* out = (float*)d_out;

    k_transpose_feat<<<dim3(N_/128, B_), 256>>>(feat);
    k_prep<<<PTS/256, 256>>>(w, x);
    k_agg<<<PTS/8, 256>>>(nidx, kern);
    k_gemm_hmma<<<PTS/64, 256>>>(bias, feat, out);
}

// round 16
// speedup vs baseline: 1.5259x; 1.5259x over previous
#include <cuda_runtime.h>
#include <cuda_fp16.h>
#include <float.h>
#include <cstdint>

#define B_   8
#define C_   64
#define N_   4096
#define K_   20
#define M_   8
#define OUTC 64
#define CM   512          // C_*M_
#define PTS  (B_*N_)      // 32768

// Scratch (allocation-free rule: __device__ globals)
__device__ __align__(16) __half g_ftH[B_*N_*C_];           // feature fp16 [b][n][c] (4 MB)
__device__ __align__(16) __half g_aggH[(size_t)PTS*CM];    // agg fp16 [pt][jperm]  (32 MB)
__device__ __align__(16) __half g_wh[CM*OUTC];             // conv_w fp16 [oc][jperm]
__device__ __align__(16) float4 g_x4[PTS];                 // packed coords (512 KB)

__device__ __forceinline__ uint32_t smem_u32(const void* p) {
    uint32_t a;
    asm("{ .reg .u64 t; cvta.to.shared.u64 t, %1; cvt.u32.u64 %0, t; }" : "=r"(a) : "l"(p));
    return a;
}
__device__ __forceinline__ void ffma2(unsigned long long& d,
                                      unsigned long long a, unsigned long long b) {
    asm("fma.rn.f32x2 %0, %1, %2, %0;" : "+l"(d) : "l"(a), "l"(b));
}
__device__ __forceinline__ unsigned long long pack2(float x, float y) {
    unsigned long long r;
    asm("mov.b64 %0, {%1, %2};" : "=l"(r) : "f"(x), "f"(y));
    return r;
}
__device__ __forceinline__ float2 unpack2(unsigned long long v) {
    float2 f;
    asm("mov.b64 {%0, %1}, %2;" : "=f"(f.x), "=f"(f.y) : "l"(v));
    return f;
}

// ===========================================================================
// K1: feature (B,C,N) fp32 -> g_ftH (B,N,C) fp16; 128n x 64c tiles
// ===========================================================================
__global__ void __launch_bounds__(256) k_transpose_feat(const float* __restrict__ feat) {
    __shared__ float tile[128][65];
    const int b   = blockIdx.y;
    const int n0  = blockIdx.x * 128;
    const int tid = threadIdx.x;
    const float* fb = feat + (size_t)b * C_ * N_;
    #pragma unroll
    for (int i = 0; i < 8; i++) {
        const int idx = tid + i * 256;      // 0..2047
        const int c   = idx >> 5;
        const int n4  = idx & 31;
        const float4 v = *(const float4*)(fb + (size_t)c * N_ + n0 + n4 * 4);
        tile[n4*4+0][c] = v.x;
        tile[n4*4+1][c] = v.y;
        tile[n4*4+2][c] = v.z;
        tile[n4*4+3][c] = v.w;
    }
    __syncthreads();
    __half* ob = g_ftH + (size_t)b * N_ * C_;
    #pragma unroll
    for (int i = 0; i < 4; i++) {
        const int idx = tid + i * 256;      // 0..1023
        const int n   = idx >> 3;
        const int q   = idx & 7;
        const float* src = &tile[n][q * 8];
        __half2 h[4];
        #pragma unroll
        for (int j = 0; j < 4; j++) h[j] = __floats2half2_rn(src[2*j], src[2*j+1]);
        *(uint4*)(ob + (size_t)(n0 + n) * C_ + q * 8) = *(uint4*)h;
    }
}

// ===========================================================================
// Prep: conv_w -> fp16 with j-permutation (exact: GEMM contracts over j and
//       A uses the same perm), x -> packed float4 per point.
//       pos in [0,256):  j = 16*(pos>>3) + (pos&7)
//       pos in [256,512): j = 16*((pos&255)>>3) + (pos&7) + 8
// ===========================================================================
__global__ void k_prep(const float* __restrict__ w, const float* __restrict__ x) {
    const int i = blockIdx.x * blockDim.x + threadIdx.x;   // 0 .. 32767
    const int oc  = i >> 9;
    const int pos = i & 511;
    const int l   = (pos >> 3) & 31;
    const int jj  = 16 * l + (pos & 7) + ((pos >> 8) << 3);
    g_wh[i] = __float2half(w[(oc << 9) + jj]);

    const int b = i >> 12;
    const int n = i & (N_ - 1);
    const float* xb = x + (size_t)b * 3 * N_;
    g_x4[i] = make_float4(xb[n], xb[N_ + n], xb[2*N_ + n], 0.f);
}

// ===========================================================================
// K3: warp-per-point (R10-proven form); launch_bounds(256,5) to lift
//     occupancy 4 -> 5 CTAs/SM; gathers split 2x10 to keep live set small.
// ===========================================================================
__global__ void __launch_bounds__(256, 5) k_agg(
    const int*   __restrict__ nidx,          // int32 (JAX x64 disabled)
    const float* __restrict__ kern)
{
    const int warp = threadIdx.x >> 5;
    const int lane = threadIdx.x & 31;
    const int pt   = blockIdx.x * 8 + warp;
    const int b    = pt >> 12;

    __shared__ float p_s[8][20][8];

    int ik = 0;
    float x0 = 0.f, x1 = 0.f, x2 = 0.f;
    if (lane < K_) {
        ik = nidx[pt * K_ + lane] & (N_ - 1);
        const float4 xv = g_x4[(b << 12) + ik];
        x0 = xv.x; x1 = xv.y; x2 = xv.z;
    }
    const float r0 = x0 - __shfl_sync(0xFFFFFFFFu, x0, 0);
    const float r1 = x1 - __shfl_sync(0xFFFFFFFFu, x1, 0);
    const float r2 = x2 - __shfl_sync(0xFFFFFFFFu, x2, 0);

    float px[8];
    #pragma unroll
    for (int m = 0; m < M_; m++) {
        float v = r0 * kern[m] + r1 * kern[M_ + m] + r2 * kern[2*M_ + m];
        if (lane == 0 && m == 0) v += 1.0f;       // one_pad
        px[m] = v;
    }
    // softmax over k (no max-shift; logits small, fp32 exp safe)
    #pragma unroll
    for (int m = 0; m < M_; m++) {
        const float e = (lane < K_) ? __expf(px[m]) : 0.f;
        float s = e;
        #pragma unroll
        for (int o = 16; o > 0; o >>= 1)
            s += __shfl_xor_sync(0xFFFFFFFFu, s, o);
        px[m] = e * (1.0f / s);
    }
    if (lane < K_) {
        float4* dst = (float4*)p_s[warp][lane];
        dst[0] = make_float4(px[0], px[1], px[2], px[3]);
        dst[1] = make_float4(px[4], px[5], px[6], px[7]);
    }
    __syncwarp();

    // aggregation: lane owns channels 2*lane, 2*lane+1; gathers in 2 batches
    const int c0 = lane * 2;
    const __half* ftb = g_ftH + ((size_t)b << 12) * C_;
    unsigned long long accA[4] = {0,0,0,0};
    unsigned long long accB[4] = {0,0,0,0};
    union f4u { float4 v; unsigned long long u[2]; };

    #pragma unroll
    for (int g = 0; g < 2; g++) {
        uint32_t f[10];
        #pragma unroll
        for (int k = 0; k < 10; k++) {
            const int ii = __shfl_sync(0xFFFFFFFFu, ik, g * 10 + k);
            f[k] = *(const uint32_t*)(ftb + (size_t)ii * C_ + c0);
        }
        #pragma unroll
        for (int k = 0; k < 10; k++) {
            const float2 fc = __half22float2(*(__half2*)&f[k]);
            const unsigned long long fxx = pack2(fc.x, fc.x);
            const unsigned long long fyy = pack2(fc.y, fc.y);
            f4u pa, pb;
            pa.v = *((const float4*)p_s[warp][g * 10 + k]);
            pb.v = *((const float4*)p_s[warp][g * 10 + k] + 1);
            ffma2(accA[0], fxx, pa.u[0]);  ffma2(accA[1], fxx, pa.u[1]);
            ffma2(accA[2], fxx, pb.u[0]);  ffma2(accA[3], fxx, pb.u[1]);
            ffma2(accB[0], fyy, pa.u[0]);  ffma2(accB[1], fyy, pa.u[1]);
            ffma2(accB[2], fyy, pb.u[0]);  ffma2(accB[3], fyy, pb.u[1]);
        }
    }

    // fp16 pack + permuted coalesced store
    __half2 h[8];
    #pragma unroll
    for (int i = 0; i < 4; i++) {
        const float2 fa = unpack2(accA[i]);
        const float2 fb = unpack2(accB[i]);
        h[i]     = __floats2half2_rn(fa.x, fa.y);
        h[4 + i] = __floats2half2_rn(fb.x, fb.y);
    }
    __half* dst = g_aggH + (size_t)pt * CM;
    *(uint4*)(dst + 8 * lane)       = *(uint4*)(h);
    *(uint4*)(dst + 256 + 8 * lane) = *(uint4*)(h + 4);
}

// ===========================================================================
// K4: HMMA fp16 GEMM, 64pt x 64oc tiles (grid 512), cp.async double buffer
//     (R10-proven config; A loads carry L2::256B prefetch hint)
// ===========================================================================
#define AS_STRIDE 72
#define BS_STRIDE 72
#define OS_STRIDE 68

struct Stage { __half a[64 * AS_STRIDE]; __half b[64 * BS_STRIDE]; };

__global__ void __launch_bounds__(256) k_gemm_hmma(
    const float* __restrict__ bias,
    const float* __restrict__ feat,
    float* __restrict__ out)
{
    __shared__ union {
        Stage st[2];
        float o[64 * OS_STRIDE];
    } sm;

    const int tid  = threadIdx.x;
    const int wid  = tid >> 5;
    const int lane = tid & 31;
    const int warp_m = (wid & 3) * 16;
    const int warp_n = (wid >> 2) * 32;
    const int ptBase = blockIdx.x * 64;

    float acc[4][4];
    #pragma unroll
    for (int ni = 0; ni < 4; ni++)
        #pragma unroll
        for (int r = 0; r < 4; r++) acc[ni][r] = 0.f;

    const __half* aSrc = g_aggH + (size_t)ptBase * CM;

    auto load_chunk = [&](int s, int kc) {
        #pragma unroll
        for (int i = 0; i < 2; i++) {
            const int c   = tid + i * 256;
            const int row = c >> 3;
            const int c8  = c & 7;
            asm volatile("cp.async.cg.shared.global.L2::256B [%0], [%1], 16;" ::
                "r"(smem_u32(sm.st[s].a + row * AS_STRIDE + c8 * 8)),
                "l"(aSrc + (size_t)row * CM + kc + c8 * 8));
        }
        #pragma unroll
        for (int i = 0; i < 2; i++) {
            const int c   = tid + i * 256;
            const int row = c >> 3;
            const int c8  = c & 7;
            asm volatile("cp.async.cg.shared.global [%0], [%1], 16;" ::
                "r"(smem_u32(sm.st[s].b + row * BS_STRIDE + c8 * 8)),
                "l"(g_wh + (size_t)row * CM + kc + c8 * 8));
        }
    };

    load_chunk(0, 0);
    asm volatile("cp.async.commit_group;");

    for (int kc8 = 0; kc8 < 8; kc8++) {
        if (kc8 < 7) {
            load_chunk((kc8 + 1) & 1, (kc8 + 1) * 64);
            asm volatile("cp.async.commit_group;");
            asm volatile("cp.async.wait_group 1;");
        } else {
            asm volatile("cp.async.wait_group 0;");
        }
        __syncthreads();

        const Stage& st = sm.st[kc8 & 1];
        #pragma unroll
        for (int ks = 0; ks < 4; ks++) {
            uint32_t a[4];
            {
                const uint32_t addr = smem_u32(
                    st.a + (warp_m + (lane & 15)) * AS_STRIDE
                         + ks * 16 + (lane >> 4) * 8);
                asm volatile("ldmatrix.sync.aligned.m8n8.x4.shared.b16 "
                             "{%0,%1,%2,%3}, [%4];"
                             : "=r"(a[0]), "=r"(a[1]), "=r"(a[2]), "=r"(a[3])
                             : "r"(addr));
            }
            uint32_t bfr[4][2];
            #pragma unroll
            for (int ni = 0; ni < 4; ni++) {
                const uint32_t addr = smem_u32(
                    st.b + (warp_n + ni * 8 + (lane & 7)) * BS_STRIDE
                         + ks * 16 + ((lane >> 3) & 1) * 8);
                asm volatile("ldmatrix.sync.aligned.m8n8.x2.shared.b16 "
                             "{%0,%1}, [%2];"
                             : "=r"(bfr[ni][0]), "=r"(bfr[ni][1])
                             : "r"(addr));
            }
            #pragma unroll
            for (int ni = 0; ni < 4; ni++) {
                asm volatile(
                    "mma.sync.aligned.m16n8k16.row.col.f32.f16.f16.f32 "
                    "{%0,%1,%2,%3}, {%4,%5,%6,%7}, {%8,%9}, {%0,%1,%2,%3};"
                    : "+f"(acc[ni][0]), "+f"(acc[ni][1]),
                      "+f"(acc[ni][2]), "+f"(acc[ni][3])
                    : "r"(a[0]), "r"(a[1]), "r"(a[2]), "r"(a[3]),
                      "r"(bfr[ni][0]), "r"(bfr[ni][1]));
            }
        }
        __syncthreads();
    }

    {
        const int r  = lane >> 2;
        const int cp = (lane & 3) * 2;
        #pragma unroll
        for (int ni = 0; ni < 4; ni++) {
            const int pt0 = warp_m + r;
            const int oc0 = warp_n + ni * 8 + cp;
            sm.o[oc0 * OS_STRIDE + pt0]           = acc[ni][0];
            sm.o[(oc0 + 1) * OS_STRIDE + pt0]     = acc[ni][1];
            sm.o[oc0 * OS_STRIDE + pt0 + 8]       = acc[ni][2];
            sm.o[(oc0 + 1) * OS_STRIDE + pt0 + 8] = acc[ni][3];
        }
    }
    __syncthreads();

    const int b  = ptBase >> 12;
    const int n0 = ptBase & (N_ - 1);
    #pragma unroll
    for (int i = 0; i < 4; i++) {
        const int c    = tid + i * 256;
        const int oc   = c >> 4;
        const int col4 = (c & 15) * 4;
        const float* src = sm.o + oc * OS_STRIDE + col4;
        const size_t o = ((size_t)(b * OUTC + oc)) * N_ + n0 + col4;
        const float4 f = *(const float4*)(feat + o);
        const float bb = bias[oc];
        float4 v;
        v.x = src[0] + bb; v.x = (v.x > 0.f ? v.x : 0.2f * v.x) + f.x;
        v.y = src[1] + bb; v.y = (v.y > 0.f ? v.y : 0.2f * v.y) + f.y;
        v.z = src[2] + bb; v.z = (v.z > 0.f ? v.z : 0.2f * v.z) + f.z;
        v.w = src[3] + bb; v.w = (v.w > 0.f ? v.w : 0.2f * v.w) + f.w;
        *(float4*)(out + o) = v;
    }
}

// ===========================================================================
extern "C" void kernel_launch(void* const* d_in, const int* in_sizes, int n_in,
                              void* d_out, int out_size) {
    const float* x    = (const float*)d_in[0];
    const float* feat = (const float*)d_in[1];
    const int*   nidx = (const int*)d_in[2];     // int32: JAX x64 is disabled
    const float* kern = (const float*)d_in[3];
    const float* w    = (const float*)d_in[4];
    const float* bias = (const float*)d_in[5];
    float* out = (float*)d_out;

    k_transpose_feat<<<dim3(N_/128, B_), 256>>>(feat);
    k_prep<<<PTS/256, 256>>>(w, x);
    k_agg<<<PTS/8, 256>>>(nidx, kern);
    k_gemm_hmma<<<PTS/64, 256>>>(bias, feat, out);
}